// round 1
// baseline (speedup 1.0000x reference)
#include <cuda_runtime.h>
#include <math.h>

#define B_   4
#define LQ   1024
#define LK   2048
#define E_   768
#define H_   16
#define HD_  48
#define BH_  (B_*H_)

// ---------------- scratch (device globals; no allocation allowed) ----------------
__device__ float g_q[BH_*LQ*HD_];                 // [b][h][lq][d]
__device__ float g_k[BH_*LK*HD_];                 // [b][h][lk][d]
__device__ float g_v[BH_*LK*HD_];                 // [b][h][lk][d]
__device__ float g_s[(size_t)BH_*LQ*LK];          // scores -> probs in place (512MB)
__device__ float g_ctx[B_*LQ*E_];                 // context  [b][lq][e]
__device__ float g_ao[B_*LQ*E_];                  // attn_output
__device__ float g_pin_part[B_*8*1536];           // partial column sums
__device__ float g_gate[B_*3];                    // (nh, sf, gv) per batch

// output layout: output | attn_weights | num_heads | scale_factor | gate_value
#define OUT_ATTN ((size_t)B_*LQ*E_)                       // 3145728
#define OUT_NH   (OUT_ATTN + (size_t)B_*LQ*LK)            // 11534336
#define OUT_SF   (OUT_NH + 4)
#define OUT_GV   (OUT_SF + 4)

// ---------------- helpers ----------------
__device__ __forceinline__ float fast_exp2(float x) {
    x = fmaxf(x, -120.0f);
    float k = rintf(x);
    float f = x - k;                      // [-0.5, 0.5]
    float p = 1.33336498e-3f;
    p = fmaf(p, f, 9.61011940e-3f);
    p = fmaf(p, f, 5.55041086e-2f);
    p = fmaf(p, f, 2.40226507e-1f);
    p = fmaf(p, f, 6.93147182e-1f);
    p = fmaf(p, f, 1.0f);
    int ik = (int)k;
    return p * __int_as_float((ik + 127) << 23);
}

__device__ __forceinline__ float block_reduce_sum(float v, float* red) {
    int tid = threadIdx.x;
    #pragma unroll
    for (int o = 16; o > 0; o >>= 1) v += __shfl_xor_sync(0xffffffffu, v, o);
    if ((tid & 31) == 0) red[tid >> 5] = v;
    __syncthreads();
    if (tid == 0) {
        float s = red[0];
        for (int i = 1; i < (int)(blockDim.x >> 5); i++) s += red[i];
        red[0] = s;
    }
    __syncthreads();
    float r = red[0];
    __syncthreads();
    return r;
}

__device__ __forceinline__ float block_reduce_max(float v, float* red) {
    int tid = threadIdx.x;
    #pragma unroll
    for (int o = 16; o > 0; o >>= 1) v = fmaxf(v, __shfl_xor_sync(0xffffffffu, v, o));
    if ((tid & 31) == 0) red[tid >> 5] = v;
    __syncthreads();
    if (tid == 0) {
        float s = red[0];
        for (int i = 1; i < (int)(blockDim.x >> 5); i++) s = fmaxf(s, red[i]);
        red[0] = s;
    }
    __syncthreads();
    float r = red[0];
    __syncthreads();
    return r;
}

// ---------------- 1) column means (partials) ----------------
__global__ void k_colmean(const float* __restrict__ q, const float* __restrict__ k) {
    int ch = blockIdx.x, b = blockIdx.y, which = blockIdx.z;
    const float* src = which ? k : q;
    int L = which ? LK : LQ;
    int rows = L / 8;
    const float* base = src + ((size_t)b * L + (size_t)ch * rows) * E_;
    for (int c = threadIdx.x; c < E_; c += 256) {
        float s = 0.f;
        for (int r = 0; r < rows; r++) s += base[(size_t)r * E_ + c];
        g_pin_part[(b * 8 + ch) * 1536 + which * E_ + c] = s;
    }
}

// ---------------- 2) gate MLP ----------------
__global__ void k_mlp(const float* __restrict__ Wp1, const float* __restrict__ bp1,
                      const float* __restrict__ Wp2, const float* __restrict__ bp2,
                      const float* __restrict__ Wp3, const float* __restrict__ bp3,
                      float* __restrict__ out) {
    __shared__ float pin[1536];
    __shared__ float h1[768];
    __shared__ float h2[384];
    int b = blockIdx.x, tid = threadIdx.x;
    for (int c = tid; c < 1536; c += 256) {
        float s = 0.f;
        for (int ch = 0; ch < 8; ch++) s += g_pin_part[(b * 8 + ch) * 1536 + c];
        pin[c] = s * ((c < 768) ? (1.0f / LQ) : (1.0f / LK));
    }
    __syncthreads();
    for (int o = tid; o < 768; o += 256) {
        const float* w = Wp1 + (size_t)o * 1536;
        float s = bp1[o];
        for (int i = 0; i < 1536; i++) s = fmaf(pin[i], w[i], s);
        h1[o] = fmaxf(s, 0.f);
    }
    __syncthreads();
    for (int o = tid; o < 384; o += 256) {
        const float* w = Wp2 + (size_t)o * 768;
        float s = bp2[o];
        for (int i = 0; i < 768; i++) s = fmaf(h1[i], w[i], s);
        h2[o] = fmaxf(s, 0.f);
    }
    __syncthreads();
    if (tid < 3) {
        const float* w = Wp3 + tid * 384;
        float s = bp3[tid];
        for (int i = 0; i < 384; i++) s = fmaf(h2[i], w[i], s);
        float sig = 1.f / (1.f + __expf(-s));
        if (tid == 0) {
            float nh = rintf(sig * 15.f + 1.f);   // round-half-even matches jnp.round
            g_gate[b * 3 + 0] = nh;
            out[OUT_NH + b] = nh;
        } else if (tid == 1) {
            float sf = sig * 0.5f + 0.5f;
            g_gate[b * 3 + 1] = sf;
            out[OUT_SF + b] = sf;
        } else {
            g_gate[b * 3 + 2] = sig;
            out[OUT_GV + b] = sig;
        }
    }
}

// ---------------- NT SGEMM body: C[128x128] += A[128xK] * B[128xK]^T ----------------
__device__ __forceinline__ void gemm_nt_body(
    const float* __restrict__ A, int lda,
    const float* __restrict__ B, int ldb,
    int K, float acc[8][8], float* sA, float* sB) {
    const int tid  = threadIdx.x;
    const int tx   = tid & 15, ty = tid >> 4;
    const int lrow = tid >> 1;
    const int lk4  = (tid & 1) * 4;
    const float* aptr = A + (size_t)lrow * lda + lk4;
    const float* bptr = B + (size_t)lrow * ldb + lk4;
    for (int k0 = 0; k0 < K; k0 += 8) {
        float4 av = *(const float4*)(aptr + k0);
        float4 bv = *(const float4*)(bptr + k0);
        __syncthreads();
        sA[(lk4 + 0) * 132 + lrow] = av.x;
        sA[(lk4 + 1) * 132 + lrow] = av.y;
        sA[(lk4 + 2) * 132 + lrow] = av.z;
        sA[(lk4 + 3) * 132 + lrow] = av.w;
        sB[(lk4 + 0) * 132 + lrow] = bv.x;
        sB[(lk4 + 1) * 132 + lrow] = bv.y;
        sB[(lk4 + 2) * 132 + lrow] = bv.z;
        sB[(lk4 + 3) * 132 + lrow] = bv.w;
        __syncthreads();
        #pragma unroll
        for (int kk = 0; kk < 8; kk++) {
            float a[8], b[8];
            *(float4*)(a)     = *(const float4*)(sA + kk * 132 + ty * 8);
            *(float4*)(a + 4) = *(const float4*)(sA + kk * 132 + ty * 8 + 4);
            *(float4*)(b)     = *(const float4*)(sB + kk * 132 + tx * 8);
            *(float4*)(b + 4) = *(const float4*)(sB + kk * 132 + tx * 8 + 4);
            #pragma unroll
            for (int i = 0; i < 8; i++)
                #pragma unroll
                for (int j = 0; j < 8; j++)
                    acc[i][j] = fmaf(a[i], b[j], acc[i][j]);
        }
    }
}

// ---------------- 3) QKV projection ----------------
__global__ void __launch_bounds__(256) k_qkv(
    const float* __restrict__ query, const float* __restrict__ key,
    const float* __restrict__ value,
    const float* __restrict__ W, const float* __restrict__ bias) {
    __shared__ float sA[8 * 132], sB[8 * 132];
    int yt = blockIdx.y;
    int z, tokbase, Lseq;
    const float* src;
    float* dst;
    if (yt < 32)      { z = 0; src = query; tokbase = yt * 128;        Lseq = LQ; dst = g_q; }
    else if (yt < 96) { z = 1; src = key;   tokbase = (yt - 32) * 128; Lseq = LK; dst = g_k; }
    else              { z = 2; src = value; tokbase = (yt - 96) * 128; Lseq = LK; dst = g_v; }
    int n0 = blockIdx.x * 128;
    float acc[8][8];
    #pragma unroll
    for (int i = 0; i < 8; i++)
        #pragma unroll
        for (int j = 0; j < 8; j++) acc[i][j] = 0.f;
    gemm_nt_body(src + (size_t)tokbase * E_, E_,
                 W + ((size_t)z * E_ + n0) * E_, E_, E_, acc, sA, sB);
    int tx = threadIdx.x & 15, ty = threadIdx.x >> 4;
    #pragma unroll
    for (int i = 0; i < 8; i++) {
        int t = tokbase + ty * 8 + i;
        int bb = t / Lseq, s = t % Lseq;
        #pragma unroll
        for (int j = 0; j < 8; j++) {
            int n = n0 + tx * 8 + j;
            int h = n / HD_, d = n % HD_;
            dst[(((size_t)(bb * H_ + h)) * Lseq + s) * HD_ + d] = acc[i][j] + bias[z * E_ + n];
        }
    }
}

// ---------------- 4) scores = QK^T / sqrt(HD), masked ----------------
__global__ void __launch_bounds__(256) k_scores(const unsigned char* __restrict__ mask) {
    __shared__ float sA[8 * 132], sB[8 * 132];
    int bh = blockIdx.z;
    int m0 = blockIdx.y * 128, n0 = blockIdx.x * 128;
    int b = bh >> 4;
    float acc[8][8];
    #pragma unroll
    for (int i = 0; i < 8; i++)
        #pragma unroll
        for (int j = 0; j < 8; j++) acc[i][j] = 0.f;
    gemm_nt_body(g_q + ((size_t)bh * LQ + m0) * HD_, HD_,
                 g_k + ((size_t)bh * LK + n0) * HD_, HD_, HD_, acc, sA, sB);
    const float scale = 0.14433757f;  // 1/sqrt(48)
    int tx = threadIdx.x & 15, ty = threadIdx.x >> 4;
    float* srow = g_s + (size_t)bh * LQ * LK;
    #pragma unroll
    for (int i = 0; i < 8; i++) {
        int m = m0 + ty * 8 + i;
        #pragma unroll
        for (int j = 0; j < 8; j++) {
            int n = n0 + tx * 8 + j;
            float v = acc[i][j] * scale;
            if (mask[b * LK + n]) v = -1e30f;
            srow[(size_t)m * LK + n] = v;
        }
    }
}

// ---------------- 5) softmax rows (in place), FMA-pipe exp ----------------
__global__ void __launch_bounds__(256) k_softmax() {
    __shared__ float red[8];
    float* p = g_s + (size_t)blockIdx.x * LK;
    int tid = threadIdx.x;
    float v[8];
    float m = -1e30f;
    #pragma unroll
    for (int i = 0; i < 8; i++) { v[i] = p[tid + i * 256]; m = fmaxf(m, v[i]); }
    m = block_reduce_max(m, red);
    float s = 0.f;
    #pragma unroll
    for (int i = 0; i < 8; i++) { v[i] = fast_exp2((v[i] - m) * 1.44269504f); s += v[i]; }
    s = block_reduce_sum(s, red);
    float inv = 1.0f / s;
    #pragma unroll
    for (int i = 0; i < 8; i++) p[tid + i * 256] = v[i] * inv;
}

// ---------------- 6) attn_weights = mean over heads ----------------
__global__ void __launch_bounds__(256) k_meanheads(float* __restrict__ out) {
    size_t idx = (size_t)blockIdx.x * 256 + threadIdx.x;   // < B*LQ*LK
    size_t per_b = (size_t)LQ * LK;
    int b = (int)(idx / per_b);
    size_t rem = idx % per_b;
    const float* base = g_s + (size_t)b * H_ * per_b + rem;
    float s = 0.f;
    #pragma unroll
    for (int h = 0; h < H_; h++) s += base[(size_t)h * per_b];
    out[OUT_ATTN + idx] = s * (1.0f / H_);
}

// ---------------- 7) ctx = P @ V ----------------
__global__ void __launch_bounds__(128) k_pv() {
    __shared__ float Ps[32 * 132];
    __shared__ float Vs[32 * 48];
    int bh = blockIdx.y;
    int m0 = blockIdx.x * 128;
    int tid = threadIdx.x;
    int tx = tid & 7, ty = tid >> 3;    // tx: 6 d-cols, ty: 8 m-rows
    const float* P = g_s + ((size_t)bh * LQ + m0) * LK;
    const float* V = g_v + (size_t)bh * LK * HD_;
    float acc[8][6];
    #pragma unroll
    for (int i = 0; i < 8; i++)
        #pragma unroll
        for (int j = 0; j < 6; j++) acc[i][j] = 0.f;
    for (int k0 = 0; k0 < LK; k0 += 32) {
        __syncthreads();
        const float* prow = P + (size_t)tid * LK + k0;
        #pragma unroll
        for (int c = 0; c < 8; c++) {
            float4 pv4 = *(const float4*)(prow + c * 4);
            Ps[(c * 4 + 0) * 132 + tid] = pv4.x;
            Ps[(c * 4 + 1) * 132 + tid] = pv4.y;
            Ps[(c * 4 + 2) * 132 + tid] = pv4.z;
            Ps[(c * 4 + 3) * 132 + tid] = pv4.w;
        }
        for (int i = tid; i < 32 * 48; i += 128)
            Vs[i] = V[(size_t)(k0 + i / 48) * HD_ + (i % 48)];
        __syncthreads();
        #pragma unroll
        for (int k = 0; k < 32; k++) {
            float a[8], bv[6];
            *(float4*)(a)     = *(const float4*)(Ps + k * 132 + ty * 8);
            *(float4*)(a + 4) = *(const float4*)(Ps + k * 132 + ty * 8 + 4);
            #pragma unroll
            for (int j = 0; j < 6; j++) bv[j] = Vs[k * 48 + tx * 6 + j];
            #pragma unroll
            for (int i = 0; i < 8; i++)
                #pragma unroll
                for (int j = 0; j < 6; j++)
                    acc[i][j] = fmaf(a[i], bv[j], acc[i][j]);
        }
    }
    int b = bh >> 4, h = bh & 15;
    #pragma unroll
    for (int i = 0; i < 8; i++) {
        int m = m0 + ty * 8 + i;
        #pragma unroll
        for (int j = 0; j < 6; j++) {
            int d = tx * 6 + j;
            g_ctx[((size_t)b * LQ + m) * E_ + h * HD_ + d] = acc[i][j];
        }
    }
}

// ---------------- 8) attn_output = ctx @ out_w^T + out_b ----------------
__global__ void __launch_bounds__(256) k_outproj(const float* __restrict__ out_w,
                                                 const float* __restrict__ out_b) {
    __shared__ float sA[8 * 132], sB[8 * 132];
    int m0 = blockIdx.y * 128, n0 = blockIdx.x * 128;
    float acc[8][8];
    #pragma unroll
    for (int i = 0; i < 8; i++)
        #pragma unroll
        for (int j = 0; j < 8; j++) acc[i][j] = 0.f;
    gemm_nt_body(g_ctx + (size_t)m0 * E_, E_, out_w + (size_t)n0 * E_, E_, E_, acc, sA, sB);
    int tx = threadIdx.x & 15, ty = threadIdx.x >> 4;
    #pragma unroll
    for (int i = 0; i < 8; i++) {
        int m = m0 + ty * 8 + i;
        #pragma unroll
        for (int j = 0; j < 8; j++) {
            int n = n0 + tx * 8 + j;
            g_ao[(size_t)m * E_ + n] = acc[i][j] + out_b[n];
        }
    }
}

// ---------------- 9) gate + residual + layernorm ----------------
__global__ void __launch_bounds__(256) k_final(const float* __restrict__ query,
                                               const float* __restrict__ ln_g,
                                               const float* __restrict__ ln_b,
                                               float* __restrict__ out) {
    __shared__ float xs[768];
    __shared__ float red[8];
    int t = blockIdx.x;
    int b = t >> 10;
    float sf = g_gate[b * 3 + 1], gv = g_gate[b * 3 + 2];
    const float* qrow = query + (size_t)t * E_;
    const float* arow = g_ao + (size_t)t * E_;
    int tid = threadIdx.x;
    float lsum = 0.f;
    for (int c = tid; c < E_; c += 256) {
        float q = qrow[c], a = arow[c];
        float gated = q * (1.f - gv) + a * sf * gv;
        float x = q + gated;
        xs[c] = x;
        lsum += x;
    }
    float mu = block_reduce_sum(lsum, red) * (1.0f / E_);
    float lv = 0.f;
    for (int c = tid; c < E_; c += 256) {
        float d = xs[c] - mu;
        lv += d * d;
    }
    float var = block_reduce_sum(lv, red) * (1.0f / E_);
    float inv = rsqrtf(var + 1e-5f);
    for (int c = tid; c < E_; c += 256)
        out[(size_t)t * E_ + c] = (xs[c] - mu) * inv * ln_g[c] + ln_b[c];
}

// ---------------- launcher ----------------
extern "C" void kernel_launch(void* const* d_in, const int* in_sizes, int n_in,
                              void* d_out, int out_size) {
    const float* query = (const float*)d_in[0];
    const float* key   = (const float*)d_in[1];
    const float* value = (const float*)d_in[2];
    const unsigned char* mask = (const unsigned char*)d_in[3];
    const float* Wp1 = (const float*)d_in[4];
    const float* bp1 = (const float*)d_in[5];
    const float* Wp2 = (const float*)d_in[6];
    const float* bp2 = (const float*)d_in[7];
    const float* Wp3 = (const float*)d_in[8];
    const float* bp3 = (const float*)d_in[9];
    const float* in_proj_w = (const float*)d_in[10];
    const float* in_proj_b = (const float*)d_in[11];
    const float* out_w = (const float*)d_in[12];
    const float* out_b = (const float*)d_in[13];
    const float* ln_g  = (const float*)d_in[14];
    const float* ln_b  = (const float*)d_in[15];
    float* out = (float*)d_out;

    k_colmean<<<dim3(8, B_, 2), 256>>>(query, key);
    k_mlp<<<B_, 256>>>(Wp1, bp1, Wp2, bp2, Wp3, bp3, out);
    k_qkv<<<dim3(6, 160), 256>>>(query, key, value, in_proj_w, in_proj_b);
    k_scores<<<dim3(16, 8, BH_), 256>>>(mask);
    k_softmax<<<BH_ * LQ, 256>>>();
    k_meanheads<<<(B_ * LQ * LK) / 256, 256>>>(out);
    k_pv<<<dim3(8, BH_), 128>>>();
    k_outproj<<<dim3(6, 32), 256>>>(out_w, out_b);
    k_final<<<B_ * LQ, 256>>>(query, ln_g, ln_b, out);
}

// round 2
// speedup vs baseline: 1.2163x; 1.2163x over previous
#include <cuda_runtime.h>
#include <math.h>

#define B_   4
#define LQ   1024
#define LK   2048
#define E_   768
#define H_   16
#define HD_  48
#define BH_  (B_*H_)

// ---------------- scratch (device globals) ----------------
__device__ float g_q[BH_*LQ*HD_];                 // [b][h][lq][d]
__device__ float g_k[BH_*LK*HD_];                 // [b][h][lk][d]
__device__ float g_v[BH_*LK*HD_];                 // [b][h][lk][d]
__device__ float g_s[(size_t)BH_*LQ*LK];          // exp(scores), unnormalized (512MB)
__device__ float g_lpart[BH_*LQ*16];              // per-ktile partial row sums
__device__ float g_linv[BH_*LQ];                  // 1/rowsum
__device__ float g_ctx[B_*LQ*E_];                 // context
__device__ float g_ao[B_*LQ*E_];                  // attn_output
__device__ float g_pin_part[B_*8*1536];
__device__ float g_gate[B_*3];

// output layout: output | attn_weights | num_heads | scale_factor | gate_value
#define OUT_ATTN ((size_t)B_*LQ*E_)
#define OUT_NH   (OUT_ATTN + (size_t)B_*LQ*LK)
#define OUT_SF   (OUT_NH + 4)
#define OUT_GV   (OUT_SF + 4)

// ---------------- helpers ----------------
__device__ __forceinline__ float fast_exp2(float x) {
    x = fmaxf(x, -120.0f);
    float k = rintf(x);
    float f = x - k;
    float p = 1.33336498e-3f;
    p = fmaf(p, f, 9.61011940e-3f);
    p = fmaf(p, f, 5.55041086e-2f);
    p = fmaf(p, f, 2.40226507e-1f);
    p = fmaf(p, f, 6.93147182e-1f);
    p = fmaf(p, f, 1.0f);
    int ik = (int)k;
    return p * __int_as_float((ik + 127) << 23);
}

__device__ __forceinline__ float block_reduce_sum(float v, float* red) {
    int tid = threadIdx.x;
    #pragma unroll
    for (int o = 16; o > 0; o >>= 1) v += __shfl_xor_sync(0xffffffffu, v, o);
    if ((tid & 31) == 0) red[tid >> 5] = v;
    __syncthreads();
    if (tid == 0) {
        float s = red[0];
        for (int i = 1; i < (int)(blockDim.x >> 5); i++) s += red[i];
        red[0] = s;
    }
    __syncthreads();
    float r = red[0];
    __syncthreads();
    return r;
}

// ---------------- 1) column means (partials) ----------------
__global__ void k_colmean(const float* __restrict__ q, const float* __restrict__ k) {
    int ch = blockIdx.x, b = blockIdx.y, which = blockIdx.z;
    const float* src = which ? k : q;
    int L = which ? LK : LQ;
    int rows = L / 8;
    const float* base = src + ((size_t)b * L + (size_t)ch * rows) * E_;
    for (int c = threadIdx.x; c < E_; c += 256) {
        float s = 0.f;
        for (int r = 0; r < rows; r++) s += base[(size_t)r * E_ + c];
        g_pin_part[(b * 8 + ch) * 1536 + which * E_ + c] = s;
    }
}

// ---------------- 2) gate MLP ----------------
__global__ void k_mlp(const float* __restrict__ Wp1, const float* __restrict__ bp1,
                      const float* __restrict__ Wp2, const float* __restrict__ bp2,
                      const float* __restrict__ Wp3, const float* __restrict__ bp3,
                      float* __restrict__ out) {
    __shared__ float pin[1536];
    __shared__ float h1[768];
    __shared__ float h2[384];
    int b = blockIdx.x, tid = threadIdx.x;
    for (int c = tid; c < 1536; c += 256) {
        float s = 0.f;
        for (int ch = 0; ch < 8; ch++) s += g_pin_part[(b * 8 + ch) * 1536 + c];
        pin[c] = s * ((c < 768) ? (1.0f / LQ) : (1.0f / LK));
    }
    __syncthreads();
    for (int o = tid; o < 768; o += 256) {
        const float* w = Wp1 + (size_t)o * 1536;
        float s = bp1[o];
        for (int i = 0; i < 1536; i++) s = fmaf(pin[i], w[i], s);
        h1[o] = fmaxf(s, 0.f);
    }
    __syncthreads();
    for (int o = tid; o < 384; o += 256) {
        const float* w = Wp2 + (size_t)o * 768;
        float s = bp2[o];
        for (int i = 0; i < 768; i++) s = fmaf(h1[i], w[i], s);
        h2[o] = fmaxf(s, 0.f);
    }
    __syncthreads();
    if (tid < 3) {
        const float* w = Wp3 + tid * 384;
        float s = bp3[tid];
        for (int i = 0; i < 384; i++) s = fmaf(h2[i], w[i], s);
        float sig = 1.f / (1.f + __expf(-s));
        if (tid == 0) {
            float nh = rintf(sig * 15.f + 1.f);
            g_gate[b * 3 + 0] = nh;
            out[OUT_NH + b] = nh;
        } else if (tid == 1) {
            float sf = sig * 0.5f + 0.5f;
            g_gate[b * 3 + 1] = sf;
            out[OUT_SF + b] = sf;
        } else {
            g_gate[b * 3 + 2] = sig;
            out[OUT_GV + b] = sig;
        }
    }
}

// ---------------- NT SGEMM body (prefetch-pipelined), 128x128, k-chunk 8 ----------------
__device__ __forceinline__ void gemm_nt_body(
    const float* __restrict__ A, int lda,
    const float* __restrict__ B, int ldb,
    int K, float acc[8][8], float* sA, float* sB) {
    const int tid  = threadIdx.x;
    const int tx   = tid & 15, ty = tid >> 4;
    const int lrow = tid >> 1;
    const int lk4  = (tid & 1) * 4;
    const float* aptr = A + (size_t)lrow * lda + lk4;
    const float* bptr = B + (size_t)lrow * ldb + lk4;
    float4 av = *(const float4*)(aptr);
    float4 bv = *(const float4*)(bptr);
    for (int k0 = 0; k0 < K; k0 += 8) {
        sA[(lk4 + 0) * 132 + lrow] = av.x;
        sA[(lk4 + 1) * 132 + lrow] = av.y;
        sA[(lk4 + 2) * 132 + lrow] = av.z;
        sA[(lk4 + 3) * 132 + lrow] = av.w;
        sB[(lk4 + 0) * 132 + lrow] = bv.x;
        sB[(lk4 + 1) * 132 + lrow] = bv.y;
        sB[(lk4 + 2) * 132 + lrow] = bv.z;
        sB[(lk4 + 3) * 132 + lrow] = bv.w;
        __syncthreads();
        if (k0 + 8 < K) {
            av = *(const float4*)(aptr + k0 + 8);
            bv = *(const float4*)(bptr + k0 + 8);
        }
        #pragma unroll
        for (int kk = 0; kk < 8; kk++) {
            float a[8], b[8];
            *(float4*)(a)     = *(const float4*)(sA + kk * 132 + ty * 8);
            *(float4*)(a + 4) = *(const float4*)(sA + kk * 132 + ty * 8 + 4);
            *(float4*)(b)     = *(const float4*)(sB + kk * 132 + tx * 8);
            *(float4*)(b + 4) = *(const float4*)(sB + kk * 132 + tx * 8 + 4);
            #pragma unroll
            for (int i = 0; i < 8; i++)
                #pragma unroll
                for (int j = 0; j < 8; j++)
                    acc[i][j] = fmaf(a[i], b[j], acc[i][j]);
        }
        __syncthreads();
    }
}

// ---------------- 3) QKV projection ----------------
__global__ void __launch_bounds__(256) k_qkv(
    const float* __restrict__ query, const float* __restrict__ key,
    const float* __restrict__ value,
    const float* __restrict__ W, const float* __restrict__ bias) {
    __shared__ float sA[8 * 132], sB[8 * 132];
    int yt = blockIdx.y;
    int z, tokbase, Lseq;
    const float* src;
    float* dst;
    if (yt < 32)      { z = 0; src = query; tokbase = yt * 128;        Lseq = LQ; dst = g_q; }
    else if (yt < 96) { z = 1; src = key;   tokbase = (yt - 32) * 128; Lseq = LK; dst = g_k; }
    else              { z = 2; src = value; tokbase = (yt - 96) * 128; Lseq = LK; dst = g_v; }
    int n0 = blockIdx.x * 128;
    float acc[8][8];
    #pragma unroll
    for (int i = 0; i < 8; i++)
        #pragma unroll
        for (int j = 0; j < 8; j++) acc[i][j] = 0.f;
    gemm_nt_body(src + (size_t)tokbase * E_, E_,
                 W + ((size_t)z * E_ + n0) * E_, E_, E_, acc, sA, sB);
    int tx = threadIdx.x & 15, ty = threadIdx.x >> 4;
    #pragma unroll
    for (int i = 0; i < 8; i++) {
        int t = tokbase + ty * 8 + i;
        int bb = t / Lseq, s = t % Lseq;
        #pragma unroll
        for (int j = 0; j < 8; j++) {
            int n = n0 + tx * 8 + j;
            int h = n / HD_, d = n % HD_;
            dst[(((size_t)(bb * H_ + h)) * Lseq + s) * HD_ + d] = acc[i][j] + bias[z * E_ + n];
        }
    }
}

// ---------------- 4) P~ = exp(QK^T/sqrt(HD)) masked, + partial row sums ----------------
__global__ void __launch_bounds__(256) k_scores_exp(const unsigned char* __restrict__ mask) {
    __shared__ float sQ[48 * 128];   // [k][m]
    __shared__ float sK[48 * 128];   // [k][n]
    int bh = blockIdx.z;
    int m0 = blockIdx.y * 128, n0 = blockIdx.x * 128;
    int b = bh >> 4;
    const float* Q = g_q + ((size_t)bh * LQ + m0) * HD_;
    const float* Kp = g_k + ((size_t)bh * LK + n0) * HD_;
    int tid = threadIdx.x;
    #pragma unroll
    for (int i = 0; i < 6; i++) {
        int idx = tid + i * 256;          // f4 index < 1536
        int r = idx / 12, c4 = idx % 12;
        float4 vq = *(const float4*)(Q + (size_t)r * HD_ + c4 * 4);
        float4 vk = *(const float4*)(Kp + (size_t)r * HD_ + c4 * 4);
        sQ[(c4 * 4 + 0) * 128 + r] = vq.x;
        sQ[(c4 * 4 + 1) * 128 + r] = vq.y;
        sQ[(c4 * 4 + 2) * 128 + r] = vq.z;
        sQ[(c4 * 4 + 3) * 128 + r] = vq.w;
        sK[(c4 * 4 + 0) * 128 + r] = vk.x;
        sK[(c4 * 4 + 1) * 128 + r] = vk.y;
        sK[(c4 * 4 + 2) * 128 + r] = vk.z;
        sK[(c4 * 4 + 3) * 128 + r] = vk.w;
    }
    __syncthreads();
    int tx = tid & 15, ty = tid >> 4;
    float acc[8][8];
    #pragma unroll
    for (int i = 0; i < 8; i++)
        #pragma unroll
        for (int j = 0; j < 8; j++) acc[i][j] = 0.f;
    #pragma unroll
    for (int kk = 0; kk < 48; kk++) {
        float a[8], bb[8];
        *(float4*)(a)      = *(const float4*)(sQ + kk * 128 + ty * 8);
        *(float4*)(a + 4)  = *(const float4*)(sQ + kk * 128 + ty * 8 + 4);
        *(float4*)(bb)     = *(const float4*)(sK + kk * 128 + tx * 8);
        *(float4*)(bb + 4) = *(const float4*)(sK + kk * 128 + tx * 8 + 4);
        #pragma unroll
        for (int i = 0; i < 8; i++)
            #pragma unroll
            for (int j = 0; j < 8; j++)
                acc[i][j] = fmaf(a[i], bb[j], acc[i][j]);
    }
    // epilogue: exp, mask, store, partial row sums
    const float cs = 0.14433757f * 1.44269504f;   // 1/sqrt(48) * log2(e)
    float mk[8];
    #pragma unroll
    for (int j = 0; j < 8; j++)
        mk[j] = mask[b * LK + n0 + tx * 8 + j] ? 0.f : 1.f;
    float* srow = g_s + (size_t)bh * LQ * LK;
    #pragma unroll
    for (int i = 0; i < 8; i++) {
        int m = m0 + ty * 8 + i;
        float p[8];
        float rs = 0.f;
        #pragma unroll
        for (int j = 0; j < 8; j++) {
            p[j] = fast_exp2(acc[i][j] * cs) * mk[j];
            rs += p[j];
        }
        float4 w0 = make_float4(p[0], p[1], p[2], p[3]);
        float4 w1 = make_float4(p[4], p[5], p[6], p[7]);
        *(float4*)(srow + (size_t)m * LK + n0 + tx * 8)     = w0;
        *(float4*)(srow + (size_t)m * LK + n0 + tx * 8 + 4) = w1;
        #pragma unroll
        for (int o = 8; o > 0; o >>= 1) rs += __shfl_xor_sync(0xffffffffu, rs, o);
        if (tx == 0)
            g_lpart[((size_t)(bh * LQ + m) << 4) + blockIdx.x] = rs;
    }
}

// ---------------- 5) reduce partial sums -> 1/l ----------------
__global__ void __launch_bounds__(256) k_lred() {
    int r = blockIdx.x * 256 + threadIdx.x;     // < BH*LQ
    float s = 0.f;
    #pragma unroll
    for (int t = 0; t < 16; t++) s += g_lpart[(size_t)r * 16 + t];
    g_linv[r] = 1.0f / s;
}

// ---------------- 6) attn_weights = mean over heads (normalized) ----------------
__global__ void __launch_bounds__(256) k_meanheads(float* __restrict__ out) {
    size_t idx = (size_t)blockIdx.x * 256 + threadIdx.x;
    size_t per_b = (size_t)LQ * LK;
    int b = (int)(idx / per_b);
    size_t rem = idx % per_b;
    int q = (int)(rem >> 11);                   // rem / LK
    const float* base = g_s + (size_t)b * H_ * per_b + rem;
    float s = 0.f;
    #pragma unroll
    for (int h = 0; h < H_; h++)
        s += base[(size_t)h * per_b] * g_linv[(b * H_ + h) * LQ + q];
    out[OUT_ATTN + idx] = s * (1.0f / H_);
}

// ---------------- 7) ctx = (P~ @ V) * (1/l) ----------------
__global__ void __launch_bounds__(256) k_pv() {
    __shared__ float Ps[32 * 128];   // [k][m]
    __shared__ float Vs[32 * 48];    // [k][d]
    int bh = blockIdx.y;
    int m0 = blockIdx.x * 128;
    int tid = threadIdx.x;
    int tx = tid & 7, ty = tid >> 3;            // tx: 6 d-cols, ty: 4 m-rows
    const float* P = g_s + ((size_t)bh * LQ + m0) * LK;
    const float* V = g_v + (size_t)bh * LK * HD_;
    float acc[4][6];
    #pragma unroll
    for (int i = 0; i < 4; i++)
        #pragma unroll
        for (int j = 0; j < 6; j++) acc[i][j] = 0.f;
    int prow = tid >> 1;
    int pc4  = (tid & 1) * 4;
    for (int k0 = 0; k0 < LK; k0 += 32) {
        __syncthreads();
        const float* pbase = P + (size_t)prow * LK + k0;
        #pragma unroll
        for (int q = 0; q < 4; q++) {
            float4 v4 = *(const float4*)(pbase + (pc4 + q) * 4);
            Ps[((pc4 + q) * 4 + 0) * 128 + prow] = v4.x;
            Ps[((pc4 + q) * 4 + 1) * 128 + prow] = v4.y;
            Ps[((pc4 + q) * 4 + 2) * 128 + prow] = v4.z;
            Ps[((pc4 + q) * 4 + 3) * 128 + prow] = v4.w;
        }
        for (int i = tid; i < 384; i += 256) {
            int r = i / 12, c = i % 12;
            float4 v4 = *(const float4*)(V + (size_t)(k0 + r) * HD_ + c * 4);
            Vs[r * 48 + c * 4 + 0] = v4.x;
            Vs[r * 48 + c * 4 + 1] = v4.y;
            Vs[r * 48 + c * 4 + 2] = v4.z;
            Vs[r * 48 + c * 4 + 3] = v4.w;
        }
        __syncthreads();
        #pragma unroll
        for (int kk = 0; kk < 32; kk++) {
            float a[4], bv[6];
            *(float4*)(a) = *(const float4*)(Ps + kk * 128 + ty * 4);
            #pragma unroll
            for (int j = 0; j < 6; j++) bv[j] = Vs[kk * 48 + tx * 6 + j];
            #pragma unroll
            for (int i = 0; i < 4; i++)
                #pragma unroll
                for (int j = 0; j < 6; j++)
                    acc[i][j] = fmaf(a[i], bv[j], acc[i][j]);
        }
    }
    int b = bh >> 4, h = bh & 15;
    #pragma unroll
    for (int i = 0; i < 4; i++) {
        int m = m0 + ty * 4 + i;
        float inv = g_linv[bh * LQ + m];
        #pragma unroll
        for (int j = 0; j < 6; j++)
            g_ctx[((size_t)b * LQ + m) * E_ + h * HD_ + tx * 6 + j] = acc[i][j] * inv;
    }
}

// ---------------- 8) attn_output = ctx @ out_w^T + out_b ----------------
__global__ void __launch_bounds__(256) k_outproj(const float* __restrict__ out_w,
                                                 const float* __restrict__ out_b) {
    __shared__ float sA[8 * 132], sB[8 * 132];
    int m0 = blockIdx.y * 128, n0 = blockIdx.x * 128;
    float acc[8][8];
    #pragma unroll
    for (int i = 0; i < 8; i++)
        #pragma unroll
        for (int j = 0; j < 8; j++) acc[i][j] = 0.f;
    gemm_nt_body(g_ctx + (size_t)m0 * E_, E_, out_w + (size_t)n0 * E_, E_, E_, acc, sA, sB);
    int tx = threadIdx.x & 15, ty = threadIdx.x >> 4;
    #pragma unroll
    for (int i = 0; i < 8; i++) {
        int m = m0 + ty * 8 + i;
        #pragma unroll
        for (int j = 0; j < 8; j++) {
            int n = n0 + tx * 8 + j;
            g_ao[(size_t)m * E_ + n] = acc[i][j] + out_b[n];
        }
    }
}

// ---------------- 9) gate + residual + layernorm ----------------
__global__ void __launch_bounds__(256) k_final(const float* __restrict__ query,
                                               const float* __restrict__ ln_g,
                                               const float* __restrict__ ln_b,
                                               float* __restrict__ out) {
    __shared__ float xs[768];
    __shared__ float red[8];
    int t = blockIdx.x;
    int b = t >> 10;
    float sf = g_gate[b * 3 + 1], gv = g_gate[b * 3 + 2];
    const float* qrow = query + (size_t)t * E_;
    const float* arow = g_ao + (size_t)t * E_;
    int tid = threadIdx.x;
    float lsum = 0.f;
    for (int c = tid; c < E_; c += 256) {
        float q = qrow[c], a = arow[c];
        float gated = q * (1.f - gv) + a * sf * gv;
        float x = q + gated;
        xs[c] = x;
        lsum += x;
    }
    float mu = block_reduce_sum(lsum, red) * (1.0f / E_);
    float lv = 0.f;
    for (int c = tid; c < E_; c += 256) {
        float d = xs[c] - mu;
        lv += d * d;
    }
    float var = block_reduce_sum(lv, red) * (1.0f / E_);
    float inv = rsqrtf(var + 1e-5f);
    for (int c = tid; c < E_; c += 256)
        out[(size_t)t * E_ + c] = (xs[c] - mu) * inv * ln_g[c] + ln_b[c];
}

// ---------------- launcher ----------------
extern "C" void kernel_launch(void* const* d_in, const int* in_sizes, int n_in,
                              void* d_out, int out_size) {
    const float* query = (const float*)d_in[0];
    const float* key   = (const float*)d_in[1];
    const float* value = (const float*)d_in[2];
    const unsigned char* mask = (const unsigned char*)d_in[3];
    const float* Wp1 = (const float*)d_in[4];
    const float* bp1 = (const float*)d_in[5];
    const float* Wp2 = (const float*)d_in[6];
    const float* bp2 = (const float*)d_in[7];
    const float* Wp3 = (const float*)d_in[8];
    const float* bp3 = (const float*)d_in[9];
    const float* in_proj_w = (const float*)d_in[10];
    const float* in_proj_b = (const float*)d_in[11];
    const float* out_w = (const float*)d_in[12];
    const float* out_b = (const float*)d_in[13];
    const float* ln_g  = (const float*)d_in[14];
    const float* ln_b  = (const float*)d_in[15];
    float* out = (float*)d_out;

    k_colmean<<<dim3(8, B_, 2), 256>>>(query, key);
    k_mlp<<<B_, 256>>>(Wp1, bp1, Wp2, bp2, Wp3, bp3, out);
    k_qkv<<<dim3(6, 160), 256>>>(query, key, value, in_proj_w, in_proj_b);
    k_scores_exp<<<dim3(16, 8, BH_), 256>>>(mask);
    k_lred<<<(BH_ * LQ) / 256, 256>>>();
    k_meanheads<<<(B_ * LQ * LK) / 256, 256>>>(out);
    k_pv<<<dim3(8, BH_), 256>>>();
    k_outproj<<<dim3(6, 32), 256>>>(out_w, out_b);
    k_final<<<B_ * LQ, 256>>>(query, ln_g, ln_b, out);
}

// round 3
// speedup vs baseline: 1.2229x; 1.0054x over previous
#include <cuda_runtime.h>
#include <math.h>

#define B_   4
#define LQ   1024
#define LK   2048
#define E_   768
#define H_   16
#define HD_  48
#define BH_  (B_*H_)

// ---------------- scratch (device globals) ----------------
__device__ float g_q[BH_*LQ*HD_];                 // [b][h][lq][d]
__device__ float g_k[BH_*LK*HD_];                 // [b][h][lk][d]
__device__ float g_v[BH_*LK*HD_];                 // [b][h][lk][d]
__device__ float g_s[(size_t)BH_*LQ*LK];          // exp(scores), unnormalized (512MB)
__device__ float g_linv[BH_*LQ];                  // 1/rowsum
__device__ float g_ctx[B_*LQ*E_];                 // context
__device__ float g_ao[B_*LQ*E_];                  // attn_output
__device__ float g_pin_part[B_*8*1536];
__device__ float g_gate[B_*3];

// output layout: output | attn_weights | num_heads | scale_factor | gate_value
#define OUT_ATTN ((size_t)B_*LQ*E_)
#define OUT_NH   (OUT_ATTN + (size_t)B_*LQ*LK)
#define OUT_SF   (OUT_NH + 4)
#define OUT_GV   (OUT_SF + 4)

// ---------------- helpers ----------------
__device__ __forceinline__ float fast_exp2(float x) {
    x = fmaxf(x, -120.0f);
    float k = rintf(x);
    float f = x - k;
    float p = 1.33336498e-3f;
    p = fmaf(p, f, 9.61011940e-3f);
    p = fmaf(p, f, 5.55041086e-2f);
    p = fmaf(p, f, 2.40226507e-1f);
    p = fmaf(p, f, 6.93147182e-1f);
    p = fmaf(p, f, 1.0f);
    int ik = (int)k;
    return p * __int_as_float((ik + 127) << 23);
}

__device__ __forceinline__ float block_reduce_sum(float v, float* red) {
    int tid = threadIdx.x;
    #pragma unroll
    for (int o = 16; o > 0; o >>= 1) v += __shfl_xor_sync(0xffffffffu, v, o);
    if ((tid & 31) == 0) red[tid >> 5] = v;
    __syncthreads();
    if (tid == 0) {
        float s = red[0];
        for (int i = 1; i < (int)(blockDim.x >> 5); i++) s += red[i];
        red[0] = s;
    }
    __syncthreads();
    float r = red[0];
    __syncthreads();
    return r;
}

// ---------------- 1) column means (partials) ----------------
__global__ void k_colmean(const float* __restrict__ q, const float* __restrict__ k) {
    int ch = blockIdx.x, b = blockIdx.y, which = blockIdx.z;
    const float* src = which ? k : q;
    int L = which ? LK : LQ;
    int rows = L / 8;
    const float* base = src + ((size_t)b * L + (size_t)ch * rows) * E_;
    for (int c = threadIdx.x; c < E_; c += 256) {
        float s = 0.f;
        for (int r = 0; r < rows; r++) s += base[(size_t)r * E_ + c];
        g_pin_part[(b * 8 + ch) * 1536 + which * E_ + c] = s;
    }
}

// ---------------- 2) gate MLP ----------------
__global__ void k_mlp(const float* __restrict__ Wp1, const float* __restrict__ bp1,
                      const float* __restrict__ Wp2, const float* __restrict__ bp2,
                      const float* __restrict__ Wp3, const float* __restrict__ bp3,
                      float* __restrict__ out) {
    __shared__ float pin[1536];
    __shared__ float h1[768];
    __shared__ float h2[384];
    int b = blockIdx.x, tid = threadIdx.x;
    for (int c = tid; c < 1536; c += 256) {
        float s = 0.f;
        for (int ch = 0; ch < 8; ch++) s += g_pin_part[(b * 8 + ch) * 1536 + c];
        pin[c] = s * ((c < 768) ? (1.0f / LQ) : (1.0f / LK));
    }
    __syncthreads();
    for (int o = tid; o < 768; o += 256) {
        const float* w = Wp1 + (size_t)o * 1536;
        float s = bp1[o];
        for (int i = 0; i < 1536; i++) s = fmaf(pin[i], w[i], s);
        h1[o] = fmaxf(s, 0.f);
    }
    __syncthreads();
    for (int o = tid; o < 384; o += 256) {
        const float* w = Wp2 + (size_t)o * 768;
        float s = bp2[o];
        for (int i = 0; i < 768; i++) s = fmaf(h1[i], w[i], s);
        h2[o] = fmaxf(s, 0.f);
    }
    __syncthreads();
    if (tid < 3) {
        const float* w = Wp3 + tid * 384;
        float s = bp3[tid];
        for (int i = 0; i < 384; i++) s = fmaf(h2[i], w[i], s);
        float sig = 1.f / (1.f + __expf(-s));
        if (tid == 0) {
            float nh = rintf(sig * 15.f + 1.f);
            g_gate[b * 3 + 0] = nh;
            out[OUT_NH + b] = nh;
        } else if (tid == 1) {
            float sf = sig * 0.5f + 0.5f;
            g_gate[b * 3 + 1] = sf;
            out[OUT_SF + b] = sf;
        } else {
            g_gate[b * 3 + 2] = sig;
            out[OUT_GV + b] = sig;
        }
    }
}

// ------ NT SGEMM body, 128x128, k-chunk 8, double-buffered (1 sync/chunk) ------
__device__ __forceinline__ void gemm_nt_body(
    const float* __restrict__ A, int lda,
    const float* __restrict__ B, int ldb,
    int K, float acc[8][8], float (*sA)[8 * 132], float (*sB)[8 * 132]) {
    const int tid  = threadIdx.x;
    const int tx   = tid & 15, ty = tid >> 4;
    const int lrow = tid >> 1;
    const int lk4  = (tid & 1) * 4;
    const float* aptr = A + (size_t)lrow * lda + lk4;
    const float* bptr = B + (size_t)lrow * ldb + lk4;
    float4 av = *(const float4*)(aptr);
    float4 bv = *(const float4*)(bptr);
    sA[0][(lk4 + 0) * 132 + lrow] = av.x;
    sA[0][(lk4 + 1) * 132 + lrow] = av.y;
    sA[0][(lk4 + 2) * 132 + lrow] = av.z;
    sA[0][(lk4 + 3) * 132 + lrow] = av.w;
    sB[0][(lk4 + 0) * 132 + lrow] = bv.x;
    sB[0][(lk4 + 1) * 132 + lrow] = bv.y;
    sB[0][(lk4 + 2) * 132 + lrow] = bv.z;
    sB[0][(lk4 + 3) * 132 + lrow] = bv.w;
    __syncthreads();
    int buf = 0;
    for (int k0 = 0; k0 < K; k0 += 8) {
        bool more = (k0 + 8) < K;
        if (more) {
            av = *(const float4*)(aptr + k0 + 8);
            bv = *(const float4*)(bptr + k0 + 8);
        }
        #pragma unroll
        for (int kk = 0; kk < 8; kk++) {
            float a[8], b[8];
            *(float4*)(a)     = *(const float4*)(sA[buf] + kk * 132 + ty * 8);
            *(float4*)(a + 4) = *(const float4*)(sA[buf] + kk * 132 + ty * 8 + 4);
            *(float4*)(b)     = *(const float4*)(sB[buf] + kk * 132 + tx * 8);
            *(float4*)(b + 4) = *(const float4*)(sB[buf] + kk * 132 + tx * 8 + 4);
            #pragma unroll
            for (int i = 0; i < 8; i++)
                #pragma unroll
                for (int j = 0; j < 8; j++)
                    acc[i][j] = fmaf(a[i], b[j], acc[i][j]);
        }
        if (more) {
            int nb = buf ^ 1;
            sA[nb][(lk4 + 0) * 132 + lrow] = av.x;
            sA[nb][(lk4 + 1) * 132 + lrow] = av.y;
            sA[nb][(lk4 + 2) * 132 + lrow] = av.z;
            sA[nb][(lk4 + 3) * 132 + lrow] = av.w;
            sB[nb][(lk4 + 0) * 132 + lrow] = bv.x;
            sB[nb][(lk4 + 1) * 132 + lrow] = bv.y;
            sB[nb][(lk4 + 2) * 132 + lrow] = bv.z;
            sB[nb][(lk4 + 3) * 132 + lrow] = bv.w;
            __syncthreads();
            buf = nb;
        }
    }
}

// ---------------- 3) QKV projection ----------------
__global__ void __launch_bounds__(256) k_qkv(
    const float* __restrict__ query, const float* __restrict__ key,
    const float* __restrict__ value,
    const float* __restrict__ W, const float* __restrict__ bias) {
    __shared__ float sA[2][8 * 132], sB[2][8 * 132];
    int yt = blockIdx.y;
    int z, tokbase, Lseq;
    const float* src;
    float* dst;
    if (yt < 32)      { z = 0; src = query; tokbase = yt * 128;        Lseq = LQ; dst = g_q; }
    else if (yt < 96) { z = 1; src = key;   tokbase = (yt - 32) * 128; Lseq = LK; dst = g_k; }
    else              { z = 2; src = value; tokbase = (yt - 96) * 128; Lseq = LK; dst = g_v; }
    int n0 = blockIdx.x * 128;
    float acc[8][8];
    #pragma unroll
    for (int i = 0; i < 8; i++)
        #pragma unroll
        for (int j = 0; j < 8; j++) acc[i][j] = 0.f;
    gemm_nt_body(src + (size_t)tokbase * E_, E_,
                 W + ((size_t)z * E_ + n0) * E_, E_, E_, acc, sA, sB);
    int tx = threadIdx.x & 15, ty = threadIdx.x >> 4;
    #pragma unroll
    for (int i = 0; i < 8; i++) {
        int t = tokbase + ty * 8 + i;
        int bb = t / Lseq, s = t % Lseq;
        #pragma unroll
        for (int j = 0; j < 8; j++) {
            int n = n0 + tx * 8 + j;
            int h = n / HD_, d = n % HD_;
            dst[(((size_t)(bb * H_ + h)) * Lseq + s) * HD_ + d] = acc[i][j] + bias[z * E_ + n];
        }
    }
}

// ------- 4) P~ = exp(QK^T/sqrt(HD)) masked, inline row sums -> g_linv -------
// CTA per (m-tile 128, bh); loops 32 n-tiles of 64. sQ resident, sK pipelined.
__global__ void __launch_bounds__(256) k_scores_exp(const unsigned char* __restrict__ mask) {
    __shared__ float sQ[48 * 128];   // [k][m], persistent
    __shared__ float sK[48 * 64];    // [k][n] current tile
    int bh = blockIdx.y;
    int m0 = blockIdx.x * 128;
    int b = bh >> 4;
    int tid = threadIdx.x;
    int tx = tid & 15, ty = tid >> 4;
    const float* Q = g_q + ((size_t)bh * LQ + m0) * HD_;
    const float* Kbase = g_k + (size_t)bh * LK * HD_;
    // load Q tile once: 1536 float4s
    #pragma unroll
    for (int i = 0; i < 6; i++) {
        int f4 = tid + i * 256;
        int r = f4 / 12, c4 = f4 % 12;
        float4 v = *(const float4*)(Q + (size_t)r * HD_ + c4 * 4);
        sQ[(c4 * 4 + 0) * 128 + r] = v.x;
        sQ[(c4 * 4 + 1) * 128 + r] = v.y;
        sQ[(c4 * 4 + 2) * 128 + r] = v.z;
        sQ[(c4 * 4 + 3) * 128 + r] = v.w;
    }
    // K-tile prefetch mapping: 768 float4s per 64x48 tile -> 3 per thread
    int rr[3], cc[3];
    #pragma unroll
    for (int i = 0; i < 3; i++) { int f4 = tid + i * 256; rr[i] = f4 / 12; cc[i] = f4 % 12; }
    float4 pk[3];
    #pragma unroll
    for (int i = 0; i < 3; i++)
        pk[i] = *(const float4*)(Kbase + (size_t)rr[i] * HD_ + cc[i] * 4);
    float rs[8];
    #pragma unroll
    for (int i = 0; i < 8; i++) rs[i] = 0.f;
    float* srow = g_s + (size_t)bh * LQ * LK;
    const float cs = 0.14433757f * 1.44269504f;   // 1/sqrt(48) * log2(e)
    for (int t = 0; t < 32; t++) {
        __syncthreads();   // previous compute done (also covers Q stores on t=0)
        #pragma unroll
        for (int i = 0; i < 3; i++) {
            sK[(cc[i] * 4 + 0) * 64 + rr[i]] = pk[i].x;
            sK[(cc[i] * 4 + 1) * 64 + rr[i]] = pk[i].y;
            sK[(cc[i] * 4 + 2) * 64 + rr[i]] = pk[i].z;
            sK[(cc[i] * 4 + 3) * 64 + rr[i]] = pk[i].w;
        }
        __syncthreads();
        if (t + 1 < 32) {
            const float* Kn = Kbase + (size_t)(t + 1) * 64 * HD_;
            #pragma unroll
            for (int i = 0; i < 3; i++)
                pk[i] = *(const float4*)(Kn + (size_t)rr[i] * HD_ + cc[i] * 4);
        }
        float acc[8][4];
        #pragma unroll
        for (int i = 0; i < 8; i++)
            #pragma unroll
            for (int j = 0; j < 4; j++) acc[i][j] = 0.f;
        #pragma unroll
        for (int kk = 0; kk < 48; kk++) {
            float a[8], bb[4];
            *(float4*)(a)     = *(const float4*)(sQ + kk * 128 + ty * 8);
            *(float4*)(a + 4) = *(const float4*)(sQ + kk * 128 + ty * 8 + 4);
            *(float4*)(bb)    = *(const float4*)(sK + kk * 64 + tx * 4);
            #pragma unroll
            for (int i = 0; i < 8; i++)
                #pragma unroll
                for (int j = 0; j < 4; j++)
                    acc[i][j] = fmaf(a[i], bb[j], acc[i][j]);
        }
        int n0 = t * 64;
        uchar4 mm = *(const uchar4*)(mask + b * LK + n0 + tx * 4);
        float mk0 = mm.x ? 0.f : 1.f;
        float mk1 = mm.y ? 0.f : 1.f;
        float mk2 = mm.z ? 0.f : 1.f;
        float mk3 = mm.w ? 0.f : 1.f;
        #pragma unroll
        for (int i = 0; i < 8; i++) {
            int m = m0 + ty * 8 + i;
            float p0 = fast_exp2(acc[i][0] * cs) * mk0;
            float p1 = fast_exp2(acc[i][1] * cs) * mk1;
            float p2 = fast_exp2(acc[i][2] * cs) * mk2;
            float p3 = fast_exp2(acc[i][3] * cs) * mk3;
            rs[i] += (p0 + p1) + (p2 + p3);
            *(float4*)(srow + (size_t)m * LK + n0 + tx * 4) = make_float4(p0, p1, p2, p3);
        }
    }
    // reduce rs over the 16 tx lanes (low 4 bits of lane id)
    #pragma unroll
    for (int i = 0; i < 8; i++) {
        #pragma unroll
        for (int o = 1; o < 16; o <<= 1)
            rs[i] += __shfl_xor_sync(0xffffffffu, rs[i], o);
    }
    if (tx == 0) {
        #pragma unroll
        for (int i = 0; i < 8; i++)
            g_linv[bh * LQ + m0 + ty * 8 + i] = 1.0f / rs[i];
    }
}

// ---------------- 6) attn_weights = mean over heads (normalized) ----------------
__global__ void __launch_bounds__(256) k_meanheads(float* __restrict__ out) {
    size_t idx4 = (size_t)blockIdx.x * 256 + threadIdx.x;   // over B*LQ*LK/4
    const size_t per_b4 = (size_t)LQ * LK / 4;
    int b = (int)(idx4 / per_b4);
    size_t rem4 = idx4 % per_b4;
    int q = (int)(rem4 >> 9);                               // rem4 / (LK/4)
    const float4* base = (const float4*)g_s + (size_t)b * H_ * per_b4 + rem4;
    float4 s = make_float4(0.f, 0.f, 0.f, 0.f);
    #pragma unroll
    for (int h = 0; h < H_; h++) {
        float inv = g_linv[(b * H_ + h) * LQ + q];
        float4 v = base[(size_t)h * per_b4];
        s.x = fmaf(v.x, inv, s.x);
        s.y = fmaf(v.y, inv, s.y);
        s.z = fmaf(v.z, inv, s.z);
        s.w = fmaf(v.w, inv, s.w);
    }
    const float ih = 1.0f / H_;
    s.x *= ih; s.y *= ih; s.z *= ih; s.w *= ih;
    ((float4*)out)[OUT_ATTN / 4 + idx4] = s;
}

// ---------------- 7) ctx = (P~ @ V) * (1/l) ----------------
__global__ void __launch_bounds__(256) k_pv() {
    __shared__ float Ps[32 * 128];   // [k][m]
    __shared__ float Vs[32 * 48];    // [k][d]
    int bh = blockIdx.y;
    int m0 = blockIdx.x * 128;
    int tid = threadIdx.x;
    int tx = tid & 7, ty = tid >> 3;            // tx: 6 d-cols, ty: 4 m-rows
    const float* P = g_s + ((size_t)bh * LQ + m0) * LK;
    const float* V = g_v + (size_t)bh * LK * HD_;
    float acc[4][6];
    #pragma unroll
    for (int i = 0; i < 4; i++)
        #pragma unroll
        for (int j = 0; j < 6; j++) acc[i][j] = 0.f;
    int prow = tid >> 1;
    int pc4  = (tid & 1) * 4;
    // V staging mapping: 384 float4s -> threads 0..127 take 2, 128..255 take 1
    int vi0 = tid;              // < 384 always for first
    int vi1 = tid + 256;        // valid if < 384
    float4 pf[4], vf0, vf1;
    const float* pbase = P + (size_t)prow * LK;
    #pragma unroll
    for (int q = 0; q < 4; q++) pf[q] = *(const float4*)(pbase + (pc4 + q) * 4);
    {
        int r = vi0 / 12, c = vi0 % 12;
        vf0 = *(const float4*)(V + (size_t)r * HD_ + c * 4);
        if (vi1 < 384) {
            int r1 = vi1 / 12, c1 = vi1 % 12;
            vf1 = *(const float4*)(V + (size_t)r1 * HD_ + c1 * 4);
        }
    }
    for (int k0 = 0; k0 < LK; k0 += 32) {
        __syncthreads();
        #pragma unroll
        for (int q = 0; q < 4; q++) {
            Ps[((pc4 + q) * 4 + 0) * 128 + prow] = pf[q].x;
            Ps[((pc4 + q) * 4 + 1) * 128 + prow] = pf[q].y;
            Ps[((pc4 + q) * 4 + 2) * 128 + prow] = pf[q].z;
            Ps[((pc4 + q) * 4 + 3) * 128 + prow] = pf[q].w;
        }
        {
            int r = vi0 / 12, c = vi0 % 12;
            *(float4*)(Vs + r * 48 + c * 4) = vf0;
            if (vi1 < 384) {
                int r1 = vi1 / 12, c1 = vi1 % 12;
                *(float4*)(Vs + r1 * 48 + c1 * 4) = vf1;
            }
        }
        __syncthreads();
        if (k0 + 32 < LK) {
            const float* pn = pbase + k0 + 32;
            #pragma unroll
            for (int q = 0; q < 4; q++) pf[q] = *(const float4*)(pn + (pc4 + q) * 4);
            const float* Vn = V + (size_t)(k0 + 32) * HD_;
            int r = vi0 / 12, c = vi0 % 12;
            vf0 = *(const float4*)(Vn + (size_t)r * HD_ + c * 4);
            if (vi1 < 384) {
                int r1 = vi1 / 12, c1 = vi1 % 12;
                vf1 = *(const float4*)(Vn + (size_t)r1 * HD_ + c1 * 4);
            }
        }
        #pragma unroll
        for (int kk = 0; kk < 32; kk++) {
            float a[4], bv[6];
            *(float4*)(a) = *(const float4*)(Ps + kk * 128 + ty * 4);
            #pragma unroll
            for (int j = 0; j < 6; j++) bv[j] = Vs[kk * 48 + tx * 6 + j];
            #pragma unroll
            for (int i = 0; i < 4; i++)
                #pragma unroll
                for (int j = 0; j < 6; j++)
                    acc[i][j] = fmaf(a[i], bv[j], acc[i][j]);
        }
    }
    int b = bh >> 4, h = bh & 15;
    #pragma unroll
    for (int i = 0; i < 4; i++) {
        int m = m0 + ty * 4 + i;
        float inv = g_linv[bh * LQ + m];
        #pragma unroll
        for (int j = 0; j < 6; j++)
            g_ctx[((size_t)b * LQ + m) * E_ + h * HD_ + tx * 6 + j] = acc[i][j] * inv;
    }
}

// ---------------- 8) attn_output = ctx @ out_w^T + out_b ----------------
__global__ void __launch_bounds__(256) k_outproj(const float* __restrict__ out_w,
                                                 const float* __restrict__ out_b) {
    __shared__ float sA[2][8 * 132], sB[2][8 * 132];
    int m0 = blockIdx.y * 128, n0 = blockIdx.x * 128;
    float acc[8][8];
    #pragma unroll
    for (int i = 0; i < 8; i++)
        #pragma unroll
        for (int j = 0; j < 8; j++) acc[i][j] = 0.f;
    gemm_nt_body(g_ctx + (size_t)m0 * E_, E_, out_w + (size_t)n0 * E_, E_, E_, acc, sA, sB);
    int tx = threadIdx.x & 15, ty = threadIdx.x >> 4;
    #pragma unroll
    for (int i = 0; i < 8; i++) {
        int m = m0 + ty * 8 + i;
        #pragma unroll
        for (int j = 0; j < 8; j++) {
            int n = n0 + tx * 8 + j;
            g_ao[(size_t)m * E_ + n] = acc[i][j] + out_b[n];
        }
    }
}

// ---------------- 9) gate + residual + layernorm ----------------
__global__ void __launch_bounds__(256) k_final(const float* __restrict__ query,
                                               const float* __restrict__ ln_g,
                                               const float* __restrict__ ln_b,
                                               float* __restrict__ out) {
    __shared__ float xs[768];
    __shared__ float red[8];
    int t = blockIdx.x;
    int b = t >> 10;
    float sf = g_gate[b * 3 + 1], gv = g_gate[b * 3 + 2];
    const float* qrow = query + (size_t)t * E_;
    const float* arow = g_ao + (size_t)t * E_;
    int tid = threadIdx.x;
    float lsum = 0.f;
    for (int c = tid; c < E_; c += 256) {
        float q = qrow[c], a = arow[c];
        float gated = q * (1.f - gv) + a * sf * gv;
        float x = q + gated;
        xs[c] = x;
        lsum += x;
    }
    float mu = block_reduce_sum(lsum, red) * (1.0f / E_);
    float lv = 0.f;
    for (int c = tid; c < E_; c += 256) {
        float d = xs[c] - mu;
        lv += d * d;
    }
    float var = block_reduce_sum(lv, red) * (1.0f / E_);
    float inv = rsqrtf(var + 1e-5f);
    for (int c = tid; c < E_; c += 256)
        out[(size_t)t * E_ + c] = (xs[c] - mu) * inv * ln_g[c] + ln_b[c];
}

// ---------------- launcher ----------------
extern "C" void kernel_launch(void* const* d_in, const int* in_sizes, int n_in,
                              void* d_out, int out_size) {
    const float* query = (const float*)d_in[0];
    const float* key   = (const float*)d_in[1];
    const float* value = (const float*)d_in[2];
    const unsigned char* mask = (const unsigned char*)d_in[3];
    const float* Wp1 = (const float*)d_in[4];
    const float* bp1 = (const float*)d_in[5];
    const float* Wp2 = (const float*)d_in[6];
    const float* bp2 = (const float*)d_in[7];
    const float* Wp3 = (const float*)d_in[8];
    const float* bp3 = (const float*)d_in[9];
    const float* in_proj_w = (const float*)d_in[10];
    const float* in_proj_b = (const float*)d_in[11];
    const float* out_w = (const float*)d_in[12];
    const float* out_b = (const float*)d_in[13];
    const float* ln_g  = (const float*)d_in[14];
    const float* ln_b  = (const float*)d_in[15];
    float* out = (float*)d_out;

    k_colmean<<<dim3(8, B_, 2), 256>>>(query, key);
    k_mlp<<<B_, 256>>>(Wp1, bp1, Wp2, bp2, Wp3, bp3, out);
    k_qkv<<<dim3(6, 160), 256>>>(query, key, value, in_proj_w, in_proj_b);
    k_scores_exp<<<dim3(8, BH_), 256>>>(mask);
    k_meanheads<<<(B_ * LQ * LK / 4) / 256, 256>>>(out);
    k_pv<<<dim3(8, BH_), 256>>>();
    k_outproj<<<dim3(6, 32), 256>>>(out_w, out_b);
    k_final<<<B_ * LQ, 256>>>(query, ln_g, ln_b, out);
}